// round 12
// baseline (speedup 1.0000x reference)
#include <cuda_runtime.h>
#include <cuda_bf16.h>
#include <cstdint>

#define BD 4
#define CD 256
#define HD 56
#define WD 56
#define GD 16
#define GCD 16
#define POSN (BD*HD*WD)   // 12544
#define IN1 2112
#define OUT1 96
#define OWD 112
#define N2 192
#define NROW (BD*HD)      // 224
#define KPGP 72           // padded kp per group (66 real)

// Scratch (device globals)
__device__ float    g_rp[2ull * POSN * OUT1];          // split partials (pre-BN)
__device__ uint32_t g_w1pth[(size_t)GD * KPGP * OUT1]; // per-group packed bf16x2 hi
__device__ uint32_t g_w1ptl[(size_t)GD * KPGP * OUT1]; // lo residual
__device__ float    g_w23h[(size_t)OUT1 * N2];
__device__ float    g_w23l[(size_t)OUT1 * N2];
__device__ float    g_wab[(size_t)POSN * N2];

// ---------------------------------------------------------------------------
// helpers
// ---------------------------------------------------------------------------
__device__ __forceinline__ uint32_t f2tf32(float f) {
    uint32_t r;
    asm("cvt.rna.tf32.f32 %0, %1;" : "=r"(r) : "f"(f));
    return r;
}
__device__ __forceinline__ void mma_tf32(float* c, const uint32_t* a, const uint32_t* b) {
    asm volatile(
        "mma.sync.aligned.m16n8k8.row.col.f32.tf32.tf32.f32 "
        "{%0,%1,%2,%3}, {%4,%5,%6,%7}, {%8,%9}, {%0,%1,%2,%3};"
        : "+f"(c[0]), "+f"(c[1]), "+f"(c[2]), "+f"(c[3])
        : "r"(a[0]), "r"(a[1]), "r"(a[2]), "r"(a[3]), "r"(b[0]), "r"(b[1]));
}
__device__ __forceinline__ void mma_bf16(float* c, const uint32_t* a, const uint32_t* b) {
    asm volatile(
        "mma.sync.aligned.m16n8k16.row.col.f32.bf16.bf16.f32 "
        "{%0,%1,%2,%3}, {%4,%5,%6,%7}, {%8,%9}, {%0,%1,%2,%3};"
        : "+f"(c[0]), "+f"(c[1]), "+f"(c[2]), "+f"(c[3])
        : "r"(a[0]), "r"(a[1]), "r"(a[2]), "r"(a[3]), "r"(b[0]), "r"(b[1]));
}
__device__ __forceinline__ uint32_t packbf(float klo, float khi) {
    uint32_t r;
    asm("cvt.rn.bf16x2.f32 %0, %1, %2;" : "=r"(r) : "f"(khi), "f"(klo));
    return r;
}
__device__ __forceinline__ float bfround(float v) {
    return __bfloat162float(__float2bfloat16(v));
}

// per-group column map (validated end-to-end in R8):
//   k <  36 : col = g*36 + k          (k = jc*9 + kh*3 + kw)
//   k <  84 : col = 576  + g*48 + (k-36)   (k-36 = gc*3 + kw)
//   k < 132 : col = 1344 + g*48 + (k-84)   (k-84 = gc*3 + kh)
__device__ __forceinline__ int colmap(int g, int k) {
    if (k < 36)  return g*36 + k;
    if (k < 84)  return 576  + g*48 + (k - 36);
    return 1344 + g*48 + (k - 84);
}

// ---------------------------------------------------------------------------
// K0a: pack per-group-reordered w1 -> bf16x2 hi/lo, [g][kp][n], kp<72 (pad 0)
// ---------------------------------------------------------------------------
__global__ __launch_bounds__(256) void w1pt_kernel(const float* __restrict__ w1) {
    int idx = blockIdx.x * 256 + threadIdx.x;
    if (idx >= GD * KPGP * OUT1) return;
    int n  = idx % OUT1;
    int kp = (idx / OUT1) % KPGP;
    int g  = idx / (OUT1 * KPGP);
    int k0 = 2*kp, k1 = 2*kp + 1;
    float v0 = (k0 < 132) ? w1[(unsigned)n * IN1 + colmap(g, k0)] : 0.f;
    float v1 = (k1 < 132) ? w1[(unsigned)n * IN1 + colmap(g, k1)] : 0.f;
    float h0 = bfround(v0), h1 = bfround(v1);
    g_w1pth[idx] = packbf(h0, h1);
    g_w1ptl[idx] = packbf(v0 - h0, v1 - h1);
}

// ---------------------------------------------------------------------------
// K0b: pre-split [w2|w3] -> [k][n] tf32 hi/lo (gemm2, unchanged)
// ---------------------------------------------------------------------------
__global__ __launch_bounds__(256) void w23split_kernel(
    const float* __restrict__ w2, const float* __restrict__ w3) {
    int idx = blockIdx.x * 256 + threadIdx.x;
    if (idx >= OUT1 * N2) return;
    int n = idx % N2;
    int k = idx / N2;
    float v = (n < OUT1) ? w2[(unsigned)n * OUT1 + k]
                         : w3[(unsigned)(n - OUT1) * OUT1 + k];
    float h = __uint_as_float(f2tf32(v));
    g_w23h[idx] = h;
    g_w23l[idx] = __uint_as_float(f2tf32(v - h));
}

// ---------------------------------------------------------------------------
// Scrambled-unfold tap descriptor value (linear taps layout
// [(gc*9 + kw*3 + kh)*58 + wp]); caller guarantees k<132, wl<56.
// ---------------------------------------------------------------------------
__device__ __forceinline__ float descval(const float* __restrict__ tp,
                                         int k, int wl,
                                         int jv0, int jv1, int jv2) {
    if (k < 36) {          // x1: max over channels {jc, jc+4, jc+8, jc+12}
        int jc = k / 9, r = k % 9, kh = r / 3, kw = r % 3;
        int jv = (kw == 0) ? jv0 : (kw == 1 ? jv1 : jv2);
        int base = (jc*9 + kw*3 + kh)*58 + wl + jv;
        return fmaxf(fmaxf(tp[base],           tp[base + 4*522]),
                     fmaxf(tp[base + 8*522],   tp[base + 12*522]));
    } else if (k < 84) {   // x2: max over kh
        int kk = k - 36, gc = kk / 3, kw = kk % 3;
        int jv = (kw == 0) ? jv0 : (kw == 1 ? jv1 : jv2);
        int base = (gc*9 + kw*3)*58 + wl + jv;
        return fmaxf(fmaxf(tp[base], tp[base + 58]), tp[base + 116]);
    } else {               // x3: max over kw
        int kk = k - 84, gc = kk / 3, kh = kk % 3;
        int base = (gc*9 + kh)*58 + wl;
        return fmaxf(fmaxf(tp[base + jv0], tp[base + 174 + jv1]),
                     tp[base + 348 + jv2]);
    }
}

// ---------------------------------------------------------------------------
// K1: FUSED descriptor + GEMM1 (3xBF16 m16n8k16).
// Grid (224 rows, 2 group-halves). Block = 256 thr, owns one (b,h2) row:
// 56 positions padded to m=64. Per group: stage taps, then 9 k-chunks of 16
// where the A tile is COMPUTED from taps (max-pool) and bf16-packed.
// Partials (no BN) to g_rp[half]; halves sum in gemm2.
// ---------------------------------------------------------------------------
#define APR 72
#define BPR 104

__global__ __launch_bounds__(256) void fgemm_kernel(const float* __restrict__ x) {
    __shared__ float    taps[GCD*9*58];                 // 33408 B
    __shared__ uint32_t Aph[8][APR], Apl[8][APR];       // 4608 B
    __shared__ uint32_t Bph[8][BPR], Bpl[8][BPR];       // 6656 B

    const int row = blockIdx.x;            // b*56 + h2
    const int half = blockIdx.y;           // groups half*8 .. half*8+7
    const int b = row / HD, h2 = row % HD;
    const int tid  = threadIdx.x;
    const int warp = tid >> 5;
    const int lane = tid & 31;
    const int wm = warp >> 2;              // 0..1 (m)
    const int wn = warp & 3;               // 0..3 (n)
    const int ar = lane >> 2;              // 0..7
    const int ac = lane & 3;               // 0..3
    const unsigned row0 = (unsigned)row * WD;

    const int jv0 = h2 % 3, jv1 = (56 + h2) % 3, jv2 = (112 + h2) % 3;

    float c[2][3][4];
    #pragma unroll
    for (int mt = 0; mt < 2; mt++)
        #pragma unroll
        for (int nt = 0; nt < 3; nt++)
            #pragma unroll
            for (int q = 0; q < 4; q++) c[mt][nt][q] = 0.f;

    const int akp = tid >> 5;              // 0..7 kp row in chunk
    const int am2 = lane * 2;              // 0..62 m pair

    for (int gi = 0; gi < 8; gi++) {
        const int g = half*8 + gi;
        // ---- stage taps for this group (same semantics as desc_kernel) ----
        const unsigned cbase = (unsigned)(b*CD + g*GCD);
        for (int idx = tid; idx < GCD*9*58; idx += 256) {
            int wp = idx % 58;
            int t  = idx / 58;             // gc*9 + kw*3 + kh
            int kh = t % 3;
            int kw = (t / 3) % 3;
            int m  = kw * 56 + h2;
            int hh = m / 3 + kh - 1;
            int ww = wp - 1;
            float v = 0.f;
            if (hh >= 0 && hh < HD && ww >= 0 && ww < WD)
                v = x[((cbase + (unsigned)(t/9))*HD + hh)*WD + ww];
            taps[idx] = v;
        }
        __syncthreads();

        // ---- 9 chunks of 16 k (72 kp padded; B zero-padded, A guarded) ----
        for (int ch = 0; ch < 9; ch++) {
            // A stage: compute 2k x 2m descriptor values, pack bf16x2 hi/lo
            {
                int kk = ch*16 + 2*akp;
                float v00 = 0.f, v01 = 0.f, v10 = 0.f, v11 = 0.f;
                if (am2 < 56) {
                    if (kk < 132) {
                        v00 = descval(taps, kk, am2,   jv0, jv1, jv2);
                        v01 = descval(taps, kk, am2+1, jv0, jv1, jv2);
                    }
                    if (kk + 1 < 132) {
                        v10 = descval(taps, kk+1, am2,   jv0, jv1, jv2);
                        v11 = descval(taps, kk+1, am2+1, jv0, jv1, jv2);
                    }
                }
                float h00 = bfround(v00), h10 = bfround(v10);
                float h01 = bfround(v01), h11 = bfround(v11);
                *reinterpret_cast<uint2*>(&Aph[akp][am2]) =
                    make_uint2(packbf(h00, h10), packbf(h01, h11));
                *reinterpret_cast<uint2*>(&Apl[akp][am2]) =
                    make_uint2(packbf(v00 - h00, v10 - h10),
                               packbf(v01 - h01, v11 - h11));
            }
            // B stage: 8 kp x 96 n pre-packed (768 u32 each)
            {
                const unsigned base = (unsigned)(g*KPGP + ch*8) * OUT1;
                #pragma unroll
                for (int i = 0; i < 3; i++) {
                    int idx = tid + (i << 8);
                    int n = idx % OUT1, kp = idx / OUT1;
                    Bph[kp][n] = g_w1pth[base + idx];
                    Bpl[kp][n] = g_w1ptl[base + idx];
                }
            }
            __syncthreads();

            uint32_t ah[2][4], al[2][4];
            #pragma unroll
            for (int mt = 0; mt < 2; mt++) {
                int mrow = wm*32 + mt*16 + ar;
                ah[mt][0] = Aph[ac  ][mrow];   ah[mt][1] = Aph[ac  ][mrow+8];
                ah[mt][2] = Aph[ac+4][mrow];   ah[mt][3] = Aph[ac+4][mrow+8];
                al[mt][0] = Apl[ac  ][mrow];   al[mt][1] = Apl[ac  ][mrow+8];
                al[mt][2] = Apl[ac+4][mrow];   al[mt][3] = Apl[ac+4][mrow+8];
            }
            uint32_t bh[3][2], bl[3][2];
            #pragma unroll
            for (int nt = 0; nt < 3; nt++) {
                int n = wn*24 + nt*8 + ar;
                bh[nt][0] = Bph[ac][n];  bh[nt][1] = Bph[ac+4][n];
                bl[nt][0] = Bpl[ac][n];  bl[nt][1] = Bpl[ac+4][n];
            }
            #pragma unroll
            for (int mt = 0; mt < 2; mt++)
                #pragma unroll
                for (int nt = 0; nt < 3; nt++) {
                    mma_bf16(c[mt][nt], ah[mt], bl[nt]);
                    mma_bf16(c[mt][nt], al[mt], bh[nt]);
                    mma_bf16(c[mt][nt], ah[mt], bh[nt]);
                }
            __syncthreads();
        }
    }

    // ---- store partials, guard local m < 56 ----
    float* rp = &g_rp[(size_t)half * POSN * OUT1];
    #pragma unroll
    for (int nt = 0; nt < 3; nt++) {
        int n0 = wn*24 + nt*8 + 2*ac;
        #pragma unroll
        for (int mt = 0; mt < 2; mt++) {
            int ml = wm*32 + mt*16 + ar;
            if (ml < 56)
                *reinterpret_cast<float2*>(&g_rp[(size_t)half*POSN*OUT1 + (row0 + ml)*OUT1 + n0]) =
                    make_float2(c[mt][nt][0], c[mt][nt][1]);
            if (ml + 8 < 56)
                *reinterpret_cast<float2*>(&g_rp[(size_t)half*POSN*OUT1 + (row0 + ml + 8)*OUT1 + n0]) =
                    make_float2(c[mt][nt][2], c[mt][nt][3]);
        }
    }
    (void)rp;
}

// ---------------------------------------------------------------------------
// K2b: GEMM2 (tf32x3, unchanged): wab = relu(BN(rp0+rp1)) @ w23 + bias
// ---------------------------------------------------------------------------
#define GBM 64
#define GBK 16
#define A2STR 72
#define B2STR 200

__global__ __launch_bounds__(256) void gemm2_kernel(
    const float* __restrict__ gamma, const float* __restrict__ beta,
    const float* __restrict__ mean,  const float* __restrict__ var,
    const float* __restrict__ b2,    const float* __restrict__ b3)
{
    __shared__ float A2h[GBK][A2STR], A2l[GBK][A2STR];
    __shared__ float B2h[GBK][B2STR], B2l[GBK][B2STR];
    __shared__ float sS[OUT1], sB[OUT1];

    const int tid  = threadIdx.x;
    const int warp = tid >> 5;
    const int lane = tid & 31;
    const int wm = warp >> 2;
    const int wn = warp & 3;
    const int ar = lane >> 2;
    const int ac = lane & 3;
    const unsigned row0 = blockIdx.x * GBM;

    if (tid < OUT1) {
        float s = gamma[tid] * rsqrtf(var[tid] + 1e-5f);
        sS[tid] = s;
        sB[tid] = beta[tid] - mean[tid] * s;
    }
    __syncthreads();

    float c[2][6][4];
    #pragma unroll
    for (int mt = 0; mt < 2; mt++)
        #pragma unroll
        for (int nt = 0; nt < 6; nt++)
            #pragma unroll
            for (int q = 0; q < 4; q++) c[mt][nt][q] = 0.f;

    const int am = tid >> 2;
    const int akq = tid & 3;

    #pragma unroll
    for (int k0 = 0; k0 < OUT1; k0 += GBK) {
        {
            int kk = k0 + akq*4;
            unsigned base = (row0 + am)*OUT1 + kk;
            float4 p0 = *reinterpret_cast<const float4*>(&g_rp[base]);
            float4 p1 = *reinterpret_cast<const float4*>(&g_rp[(size_t)POSN*OUT1 + base]);
            float v[4] = {p0.x+p1.x, p0.y+p1.y, p0.z+p1.z, p0.w+p1.w};
            #pragma unroll
            for (int i = 0; i < 4; i++) {
                float r = fmaxf(fmaf(v[i], sS[kk+i], sB[kk+i]), 0.f);
                float h = __uint_as_float(f2tf32(r));
                A2h[akq*4 + i][am] = h;
                A2l[akq*4 + i][am] = __uint_as_float(f2tf32(r - h));
            }
        }
        {
            const unsigned base = (unsigned)k0 * N2;
            #pragma unroll
            for (int i = 0; i < 12; i++) {
                int idx = tid + (i << 8);
                int n = idx % N2, k = idx / N2;
                B2h[k][n] = g_w23h[base + idx];
                B2l[k][n] = g_w23l[base + idx];
            }
        }
        __syncthreads();

        #pragma unroll
        for (int ks = 0; ks < 2; ks++) {
            const int kb = ks * 8;
            uint32_t ah[2][4], al[2][4];
            #pragma unroll
            for (int mt = 0; mt < 2; mt++) {
                int mrow = wm*32 + mt*16 + ar;
                ah[mt][0] = __float_as_uint(A2h[kb+ac  ][mrow  ]);
                ah[mt][1] = __float_as_uint(A2h[kb+ac  ][mrow+8]);
                ah[mt][2] = __float_as_uint(A2h[kb+ac+4][mrow  ]);
                ah[mt][3] = __float_as_uint(A2h[kb+ac+4][mrow+8]);
                al[mt][0] = __float_as_uint(A2l[kb+ac  ][mrow  ]);
                al[mt][1] = __float_as_uint(A2l[kb+ac  ][mrow+8]);
                al[mt][2] = __float_as_uint(A2l[kb+ac+4][mrow  ]);
                al[mt][3] = __float_as_uint(A2l[kb+ac+4][mrow+8]);
            }
            uint32_t bh[6][2], bl[6][2];
            #pragma unroll
            for (int nt = 0; nt < 6; nt++) {
                int n = wn*48 + nt*8 + ar;
                bh[nt][0] = __float_as_uint(B2h[kb+ac  ][n]);
                bh[nt][1] = __float_as_uint(B2h[kb+ac+4][n]);
                bl[nt][0] = __float_as_uint(B2l[kb+ac  ][n]);
                bl[nt][1] = __float_as_uint(B2l[kb+ac+4][n]);
            }
            #pragma unroll
            for (int mt = 0; mt < 2; mt++)
                #pragma unroll
                for (int nt = 0; nt < 6; nt++) {
                    mma_tf32(c[mt][nt], ah[mt], bl[nt]);
                    mma_tf32(c[mt][nt], al[mt], bh[nt]);
                    mma_tf32(c[mt][nt], ah[mt], bh[nt]);
                }
        }
        __syncthreads();
    }

    #pragma unroll
    for (int nt = 0; nt < 6; nt++) {
        int n0 = wn*48 + nt*8 + 2*ac;
        float bias0 = (n0 < OUT1) ? b2[n0] : b3[n0 - OUT1];
        float bias1 = (n0 + 1 < OUT1) ? b2[n0 + 1] : b3[n0 + 1 - OUT1];
        #pragma unroll
        for (int mt = 0; mt < 2; mt++) {
            unsigned m0 = row0 + wm*32 + mt*16 + ar;
            *reinterpret_cast<float2*>(&g_wab[(size_t)m0*N2 + n0]) =
                make_float2(c[mt][nt][0] + bias0, c[mt][nt][1] + bias1);
            *reinterpret_cast<float2*>(&g_wab[(size_t)(m0+8)*N2 + n0]) =
                make_float2(c[mt][nt][2] + bias0, c[mt][nt][3] + bias1);
        }
    }
}

// ---------------------------------------------------------------------------
// K3: apply (unchanged)
// ---------------------------------------------------------------------------
__device__ __forceinline__ void load_taps(const float* __restrict__ x,
                                          int b, int g, int h2,
                                          float (*xs)[3][3][58], int tid) {
    const unsigned cbase = (unsigned)(b*CD + g*GCD);
    for (int idx = tid; idx < GCD * 9 * 58; idx += 128) {
        int wp = idx % 58;
        int t  = idx / 58;
        int kh = t % 3;
        int kw = (t / 3) % 3;
        int gc = t / 9;
        int m  = kw * 56 + h2;
        int hh = m / 3 + kh - 1;
        int ww = wp - 1;
        float v = 0.f;
        if (hh >= 0 && hh < HD && ww >= 0 && ww < WD)
            v = x[((cbase + gc)*HD + hh)*WD + ww];
        xs[gc][kw][kh][wp] = v;
    }
}

__global__ __launch_bounds__(128) void apply_kernel(
    const float* __restrict__ x, float* __restrict__ out)
{
    const int g = blockIdx.x, h2 = blockIdx.y, b = blockIdx.z;
    __shared__ float xs[GCD][3][3][58];
    __shared__ float wab[WD][12];
    __shared__ float sms[WD*37];

    const int tid = threadIdx.x;
    const unsigned posBase = (unsigned)(b*HD + h2)*WD;

    for (int it = tid; it < WD * 12; it += 128) {
        int q = it % 12;
        int w = it / 12;
        int col = (q < 6) ? (g*6 + q) : (OUT1 + g*6 + q - 6);
        wab[w][q] = g_wab[(size_t)(posBase + w)*N2 + col];
    }
    load_taps(x, b, g, h2, xs, tid);
    __syncthreads();

    for (int it = tid; it < WD * 4; it += 128) {
        int t = it % 4;
        int w = it / 4;
        int nh = t >> 1, nw = t & 1;
        float e[9], m = -1e30f;
        #pragma unroll
        for (int kk = 0; kk < 9; kk++) {
            int kh = kk / 3, kw = kk % 3;
            e[kk] = wab[w][kh*2 + nh] * wab[w][6 + kw*2 + nw];
            m = fmaxf(m, e[kk]);
        }
        float s = 0.f;
        #pragma unroll
        for (int kk = 0; kk < 9; kk++) { e[kk] = expf(e[kk] - m); s += e[kk]; }
        float inv = 1.f / (s * 9.f);
        #pragma unroll
        for (int kk = 0; kk < 9; kk++) sms[w*37 + t*9 + kk] = e[kk] * inv;
    }
    __syncthreads();

    const int jv0 = h2 % 3, jv1 = (56 + h2) % 3, jv2 = (112 + h2) % 3;
    const int jvv[3] = {jv0, jv1, jv2};

    for (int it = tid; it < GCD * WD; it += 128) {
        int w  = it % WD;
        int gc = it / WD;
        float o[4] = {0.f, 0.f, 0.f, 0.f};
        #pragma unroll
        for (int kk = 0; kk < 9; kk++) {
            int kh = kk / 3, kw = kk % 3;
            float u = xs[gc][kw][kh][w + jvv[kw]];
            #pragma unroll
            for (int t = 0; t < 4; t++)
                o[t] = fmaf(u, sms[w*37 + t*9 + kk], o[t]);
        }
        int c = g*GCD + gc;
        #pragma unroll
        for (int t = 0; t < 4; t++) {
            int nh = t >> 1, nw = t & 1;
            out[(((unsigned)(b*CD + c))*OWD + 2*h2 + nh)*OWD + 2*w + nw] = o[t];
        }
    }
}

// ---------------------------------------------------------------------------
extern "C" void kernel_launch(void* const* d_in, const int* in_sizes, int n_in,
                              void* d_out, int out_size) {
    const float* x     = (const float*)d_in[0];
    const float* w1    = (const float*)d_in[1];
    const float* gamma = (const float*)d_in[2];
    const float* beta  = (const float*)d_in[3];
    const float* mean  = (const float*)d_in[4];
    const float* var   = (const float*)d_in[5];
    const float* w2    = (const float*)d_in[6];
    const float* b2    = (const float*)d_in[7];
    const float* w3    = (const float*)d_in[8];
    const float* b3    = (const float*)d_in[9];
    float* out = (float*)d_out;

    w1pt_kernel<<<(GD*KPGP*OUT1 + 255)/256, 256>>>(w1);
    w23split_kernel<<<(OUT1*N2 + 255)/256, 256>>>(w2, w3);
    fgemm_kernel<<<dim3(NROW, 2), 256>>>(x);
    gemm2_kernel<<<POSN / GBM, 256>>>(gamma, beta, mean, var, b2, b3);
    apply_kernel<<<dim3(GD, HD, BD), 128>>>(x, out);
}